// round 11
// baseline (speedup 1.0000x reference)
#include <cuda_runtime.h>
#include <cuda_bf16.h>

// ChamferDistance: B=4, C=3, N=M=8192, fp32 -> scalar.
// DUAL-REDUCTION: t(n,m) = x.y - hx - hy = -0.5*||x-y||^2 <= 0 is shared by both
// Chamfer directions:  min_m dist(n,.) = -2*max_m t,  min_n dist(.,m) = -2*max_n t.
// One pass computes both -> HALF the FMA work of the single-direction engine.
//   m-side max: persistent registers (thread owns QM=8 target points).
//   n-side max: per-thread scalar STS into a 32x256 smem matrix (hot loop pays
//               7 FMNMX + 1 STS per n), reduced in a deferred per-chunk phase.
// Cross-block merge: raw-bit atomicMin (umin == fmax for non-positive floats).
// Snake partition (R10): G=444 blocks, contiguous ranges of 131072 n-units.

#define NPTS    8192
#define NBATCH  4
#define THREADS 256
#define QM      8                     // target points per thread (persistent)
#define MTILE   (THREADS * QM)        // 2048 m per super-unit
#define NMT     (NPTS / MTILE)        // 4 m-tiles
#define NSU     (NBATCH * NMT)        // 16 super-units (b, mt)
#define TOT_N   (NSU * NPTS)          // 131072 n-units
#define G       444                   // 3 CTAs/SM x 148 SMs
#define NCH     32                    // n's per chunk
#define NKEYS   (2 * NBATCH * NPTS)   // 65536: [0..32767] pred(n), rest targ(m)
#define NEG_INF (-3.402823466e38f)

__device__ unsigned g_key[NKEYS];
__device__ unsigned g_count;

typedef unsigned long long u64;

__device__ __forceinline__ u64 fma2(u64 a, u64 b, u64 c) {
    u64 d;
    asm("fma.rn.f32x2 %0, %1, %2, %3;" : "=l"(d) : "l"(a), "l"(b), "l"(c));
    return d;
}
__device__ __forceinline__ u64 pack_ab(float lo, float hi) {
    u64 d;
    asm("mov.b64 %0, {%1, %2};" : "=l"(d) : "f"(lo), "f"(hi));
    return d;
}
__device__ __forceinline__ void unpack2(u64 v, float& lo, float& hi) {
    asm("mov.b64 {%0, %1}, %2;" : "=f"(lo), "=f"(hi) : "l"(v));
}
__device__ __forceinline__ void lds_v2u64(unsigned addr, u64& a, u64& b) {
    asm volatile("ld.shared.v2.u64 {%0, %1}, [%2];" : "=l"(a), "=l"(b) : "r"(addr));
}

__global__ void chamfer_init_kernel() {
    int i = blockIdx.x * blockDim.x + threadIdx.x;
    g_key[i] = 0xFFFFFFFFu;   // umin identity
    if (i == 0) g_count = 0u;
}

__global__ __launch_bounds__(THREADS)
void chamfer_main_kernel(const float* __restrict__ pred,
                         const float* __restrict__ targ,
                         float* __restrict__ out) {
    const int tid  = threadIdx.x;
    const int lane = tid & 31;
    const int wid  = tid >> 5;

    __shared__ float4 s_n[NCH * 2];           // per n: {x0,x0,x1,x1},{x2,x2,nhx,nhx}
    __shared__ float  s_part[NCH * THREADS];  // per (n, thread) partial max
    __shared__ float  wsum[THREADS / 32];
    __shared__ unsigned s_flag;

    const unsigned snb = (unsigned)__cvta_generic_to_shared(s_n);

    int it            = (int)(((long long)blockIdx.x * TOT_N) / G);
    const int it_last = (int)(((long long)(blockIdx.x + 1) * TOT_N) / G);

    while (it < it_last) {
        const int su   = it >> 13;                       // / NPTS
        const int sEnd = min(it_last, (su + 1) << 13);
        const int b    = su >> 2;
        const int mt   = su & 3;

        const float* __restrict__ X = pred + (size_t)b * 3 * NPTS;  // n-side (pred)
        const float* __restrict__ Y = targ + (size_t)b * 3 * NPTS;  // m-side (targ)

        // ---- persistent m-tile: QM=8 targets/thread, packed pairs ----
        const int m0 = mt * MTILE + tid * QM;
        u64 Y0p[QM/2], Y1p[QM/2], Y2p[QM/2], NHp[QM/2];
        {
            float y0[QM], y1[QM], y2[QM];
            const float4* P0 = (const float4*)(Y + m0);
            const float4* P1 = (const float4*)(Y + NPTS + m0);
            const float4* P2 = (const float4*)(Y + 2 * NPTS + m0);
            float4 a, c;
            a = P0[0]; c = P0[1];
            y0[0]=a.x; y0[1]=a.y; y0[2]=a.z; y0[3]=a.w; y0[4]=c.x; y0[5]=c.y; y0[6]=c.z; y0[7]=c.w;
            a = P1[0]; c = P1[1];
            y1[0]=a.x; y1[1]=a.y; y1[2]=a.z; y1[3]=a.w; y1[4]=c.x; y1[5]=c.y; y1[6]=c.z; y1[7]=c.w;
            a = P2[0]; c = P2[1];
            y2[0]=a.x; y2[1]=a.y; y2[2]=a.z; y2[3]=a.w; y2[4]=c.x; y2[5]=c.y; y2[6]=c.z; y2[7]=c.w;
            #pragma unroll
            for (int k = 0; k < QM/2; k++) {
                float nl_ = -0.5f * (y0[2*k]*y0[2*k] + y1[2*k]*y1[2*k] + y2[2*k]*y2[2*k]);
                float nh_ = -0.5f * (y0[2*k+1]*y0[2*k+1] + y1[2*k+1]*y1[2*k+1] + y2[2*k+1]*y2[2*k+1]);
                Y0p[k] = pack_ab(y0[2*k], y0[2*k+1]);
                Y1p[k] = pack_ab(y1[2*k], y1[2*k+1]);
                Y2p[k] = pack_ab(y2[2*k], y2[2*k+1]);
                NHp[k] = pack_ab(nl_, nh_);
            }
        }
        const u64 ONESp = pack_ab(1.0f, 1.0f);

        float my[QM];
        #pragma unroll
        for (int j = 0; j < QM; j++) my[j] = NEG_INF;

        const int nbase = it - (su << 13);
        const int nEnd  = sEnd - (su << 13);

        for (int t = nbase; t < nEnd; t += NCH) {
            const int cnt = min(NCH, nEnd - t);
            __syncthreads();   // protect s_n/s_part from previous chunk

            // ---- stage chunk of n-points (duplicated pairs) ----
            if (tid < cnt) {
                int n = t + tid;
                float x0 = X[n];
                float x1 = X[NPTS + n];
                float x2 = X[2 * NPTS + n];
                float nhx = -0.5f * (x0*x0 + x1*x1 + x2*x2);
                s_n[tid * 2 + 0] = make_float4(x0, x0, x1, x1);
                s_n[tid * 2 + 1] = make_float4(x2, x2, nhx, nhx);
            }
            __syncthreads();

            // ---- hot loop: 8 dual-evals per thread per n ----
            #pragma unroll 2
            for (int nl = 0; nl < cnt; nl++) {
                u64 xA, xB, xC, xH;
                lds_v2u64(snb + nl * 32, xA, xB);
                lds_v2u64(snb + nl * 32 + 16, xC, xH);

                u64 t0 = fma2(xH, ONESp, NHp[0]);   // nhx + nhy
                u64 t1 = fma2(xH, ONESp, NHp[1]);
                u64 t2 = fma2(xH, ONESp, NHp[2]);
                u64 t3 = fma2(xH, ONESp, NHp[3]);
                t0 = fma2(xA, Y0p[0], t0);
                t1 = fma2(xA, Y0p[1], t1);
                t2 = fma2(xA, Y0p[2], t2);
                t3 = fma2(xA, Y0p[3], t3);
                t0 = fma2(xB, Y1p[0], t0);
                t1 = fma2(xB, Y1p[1], t1);
                t2 = fma2(xB, Y1p[2], t2);
                t3 = fma2(xB, Y1p[3], t3);
                t0 = fma2(xC, Y2p[0], t0);
                t1 = fma2(xC, Y2p[1], t1);
                t2 = fma2(xC, Y2p[2], t2);
                t3 = fma2(xC, Y2p[3], t3);

                float v0, v1, v2, v3, v4, v5, v6, v7;
                unpack2(t0, v0, v1);
                unpack2(t1, v2, v3);
                unpack2(t2, v4, v5);
                unpack2(t3, v6, v7);

                my[0] = fmaxf(my[0], v0);
                my[1] = fmaxf(my[1], v1);
                my[2] = fmaxf(my[2], v2);
                my[3] = fmaxf(my[3], v3);
                my[4] = fmaxf(my[4], v4);
                my[5] = fmaxf(my[5], v5);
                my[6] = fmaxf(my[6], v6);
                my[7] = fmaxf(my[7], v7);

                float p0 = fmaxf(v0, v1), p1 = fmaxf(v2, v3);
                float p2 = fmaxf(v4, v5), p3 = fmaxf(v6, v7);
                s_part[nl * THREADS + tid] = fmaxf(fmaxf(p0, p1), fmaxf(p2, p3));
            }
            __syncthreads();

            // ---- deferred n-side reduce: warp w handles n = w*4+i ----
            #pragma unroll
            for (int i = 0; i < 4; i++) {
                int n = wid * 4 + i;
                if (n < cnt) {
                    const float* row = &s_part[n * THREADS];
                    float v = row[lane];
                    #pragma unroll
                    for (int j = 1; j < 8; j++)
                        v = fmaxf(v, row[lane + 32 * j]);   // conflict-free columns
                    #pragma unroll
                    for (int off = 16; off > 0; off >>= 1)
                        v = fmaxf(v, __shfl_xor_sync(0xffffffffu, v, off));
                    if (lane == 0)
                        atomicMin(&g_key[b * NPTS + t + n], __float_as_uint(v));
                }
            }
        }

        // ---- m-side segment epilogue ----
        const int mkey0 = (NBATCH + b) * NPTS + m0;
        #pragma unroll
        for (int j = 0; j < QM; j++)
            atomicMin(&g_key[mkey0 + j], __float_as_uint(my[j]));

        it = sEnd;
    }

    // ---- last block performs the final sum ----
    __threadfence();
    __syncthreads();
    if (tid == 0)
        s_flag = (atomicAdd(&g_count, 1u) == (unsigned)(G - 1)) ? 1u : 0u;
    __syncthreads();
    if (s_flag) {
        const uint4* kp = (const uint4*)g_key;
        float sa = 0.0f, sb = 0.0f, sc = 0.0f, sd = 0.0f;
        for (int i = tid; i < NKEYS / 4; i += THREADS) {
            uint4 v = __ldcg(&kp[i]);
            sa += __uint_as_float(v.x);
            sb += __uint_as_float(v.y);
            sc += __uint_as_float(v.z);
            sd += __uint_as_float(v.w);
        }
        float s = (sa + sb) + (sc + sd);
        #pragma unroll
        for (int off = 16; off > 0; off >>= 1)
            s += __shfl_xor_sync(0xffffffffu, s, off);
        if ((tid & 31) == 0) wsum[tid >> 5] = s;
        __syncthreads();
        if (tid == 0) {
            float tsum = 0.0f;
            #pragma unroll
            for (int i = 0; i < THREADS / 32; i++) tsum += wsum[i];
            // min dist per point = -2 * t_full; two means each over B*NPTS
            out[0] = tsum * (-2.0f / (float)(NBATCH * NPTS));
        }
    }
}

extern "C" void kernel_launch(void* const* d_in, const int* in_sizes, int n_in,
                              void* d_out, int out_size) {
    const float* pred = (const float*)d_in[0];
    const float* targ = (const float*)d_in[1];
    float* out = (float*)d_out;

    chamfer_init_kernel<<<NKEYS / 1024, 1024>>>();
    chamfer_main_kernel<<<G, THREADS>>>(pred, targ, out);
}

// round 12
// speedup vs baseline: 1.0036x; 1.0036x over previous
#include <cuda_runtime.h>
#include <cuda_bf16.h>

// ChamferDistance: B=4, C=3, N=M=8192, fp32 -> scalar.
// R12 = exact R2 geometry/engine (best measured: 80.4us) + proven deltas only:
//   - raw-bit atomicMin merge (t_full <= 0: float-max == uint-min on bits)
//   - fused last-block final sum (no third launch)
// Engine: t = x.y - 0.5||y||^2; per-query max; t_full = max - hx.
// THREADS=128, QPT=4 packed {x,x} broadcast regs, TCHUNK=512, unroll 2,
// 2048 blocks = (2 dir x 4 b x 16 qt x 16 tc).

#define NPTS    8192
#define NBATCH  4
#define THREADS 128
#define QPT     4
#define QTILE   (THREADS * QPT)          // 512 queries per block
#define NQT     (NPTS / QTILE)           // 16
#define TCHUNK  512                      // targets per block
#define NTC     (NPTS / TCHUNK)          // 16
#define NBLOCKS (2 * NBATCH * NQT * NTC) // 2048
#define NKEYS   (2 * NBATCH * NPTS)      // 65536
#define NEG_INF (-3.402823466e38f)

__device__ unsigned g_key[NKEYS];   // raw bits of t_full (<=0), merged via umin
__device__ unsigned g_count;

typedef unsigned long long u64;

__device__ __forceinline__ u64 fma2(u64 a, u64 b, u64 c) {
    u64 d;
    asm("fma.rn.f32x2 %0, %1, %2, %3;" : "=l"(d) : "l"(a), "l"(b), "l"(c));
    return d;
}
__device__ __forceinline__ u64 pack2(float x) {
    u64 d;
    asm("mov.b64 %0, {%1, %1};" : "=l"(d) : "f"(x));
    return d;
}
__device__ __forceinline__ void unpack2(u64 v, float& lo, float& hi) {
    asm("mov.b64 {%0, %1}, %2;" : "=f"(lo), "=f"(hi) : "l"(v));
}
__device__ __forceinline__ void lds_v2u64(unsigned addr, u64& a, u64& b) {
    asm volatile("ld.shared.v2.u64 {%0, %1}, [%2];" : "=l"(a), "=l"(b) : "r"(addr));
}

__global__ void chamfer_init_kernel() {
    int i = blockIdx.x * blockDim.x + threadIdx.x;
    g_key[i] = 0xFFFFFFFFu;   // umin identity
    if (i == 0) g_count = 0u;
}

__global__ __launch_bounds__(THREADS)
void chamfer_main_kernel(const float* __restrict__ pred,
                         const float* __restrict__ targ,
                         float* __restrict__ out) {
    const int u   = blockIdx.x;
    const int tc  = u & (NTC - 1);
    const int qt  = (u >> 4) & (NQT - 1);
    const int b   = (u >> 8) & (NBATCH - 1);
    const int dir = u >> 10;

    const float* __restrict__ X = (dir ? targ : pred) + (size_t)b * 3 * NPTS;  // queries
    const float* __restrict__ Y = (dir ? pred : targ) + (size_t)b * 3 * NPTS;  // targets

    __shared__ float s_y0[TCHUNK], s_y1[TCHUNK], s_y2[TCHUNK], s_nh[TCHUNK];
    __shared__ float wsum[THREADS / 32];
    __shared__ unsigned s_flag;

    const int tid = threadIdx.x;

    // ---- stage target chunk SoA: y0, y1, y2, nh = -0.5*||y||^2 ----
    const int tbase = tc * TCHUNK;
    #pragma unroll
    for (int i = tid; i < TCHUNK; i += THREADS) {
        float y0 = Y[tbase + i];
        float y1 = Y[NPTS + tbase + i];
        float y2 = Y[2 * NPTS + tbase + i];
        s_y0[i] = y0;
        s_y1[i] = y1;
        s_y2[i] = y2;
        s_nh[i] = -0.5f * (y0 * y0 + y1 * y1 + y2 * y2);
    }

    // ---- QPT queries per thread: packed broadcast registers ----
    const int qbase = qt * QTILE;
    u64 xp0[QPT], xp1[QPT], xp2[QPT];
    float hx[QPT];
    #pragma unroll
    for (int q = 0; q < QPT; q++) {
        int n = qbase + q * THREADS + tid;
        float x0 = X[n];
        float x1 = X[NPTS + n];
        float x2 = X[2 * NPTS + n];
        xp0[q] = pack2(x0);
        xp1[q] = pack2(x1);
        xp2[q] = pack2(x2);
        hx[q] = 0.5f * (x0 * x0 + x1 * x1 + x2 * x2);
    }
    __syncthreads();

    const unsigned a0 = (unsigned)__cvta_generic_to_shared(s_y0);
    const unsigned a1 = (unsigned)__cvta_generic_to_shared(s_y1);
    const unsigned a2 = (unsigned)__cvta_generic_to_shared(s_y2);
    const unsigned ah = (unsigned)__cvta_generic_to_shared(s_nh);

    float m0[QPT], m1[QPT];
    #pragma unroll
    for (int q = 0; q < QPT; q++) { m0[q] = NEG_INF; m1[q] = NEG_INF; }

    // ---- main loop: 4 targets/iter (broadcast LDS), 4 queries/thread ----
    #pragma unroll 2
    for (int j = 0; j < TCHUNK / 4; j++) {
        u64 A0, A1, B0, B1, C0, C1, H0, H1;
        const unsigned off = j * 16;
        lds_v2u64(a0 + off, A0, A1);   // y0[4j..4j+3] as two packed pairs
        lds_v2u64(a1 + off, B0, B1);
        lds_v2u64(a2 + off, C0, C1);
        lds_v2u64(ah + off, H0, H1);

        #pragma unroll
        for (int q = 0; q < QPT; q++) {
            u64 t0 = fma2(xp2[q], C0, H0);
            u64 t1 = fma2(xp2[q], C1, H1);
            t0 = fma2(xp1[q], B0, t0);
            t1 = fma2(xp1[q], B1, t1);
            t0 = fma2(xp0[q], A0, t0);
            t1 = fma2(xp0[q], A1, t1);
            float l0, h0, l1, h1;
            unpack2(t0, l0, h0);
            unpack2(t1, l1, h1);
            m0[q] = fmaxf(m0[q], l0);
            m1[q] = fmaxf(m1[q], h0);
            m0[q] = fmaxf(m0[q], l1);
            m1[q] = fmaxf(m1[q], h1);
        }
    }

    // ---- epilogue: t_full = max - hx <= 0, merge via raw-bit umin ----
    const int key0 = (dir * NBATCH + b) * NPTS + qbase + tid;
    #pragma unroll
    for (int q = 0; q < QPT; q++) {
        float tf = fmaxf(m0[q], m1[q]) - hx[q];
        atomicMin(&g_key[key0 + q * THREADS], __float_as_uint(tf));
    }

    // ---- last block performs the final sum (fused reduce) ----
    __threadfence();
    if (tid == 0)
        s_flag = (atomicAdd(&g_count, 1u) == (unsigned)(NBLOCKS - 1)) ? 1u : 0u;
    __syncthreads();
    if (s_flag) {
        const uint4* kp = (const uint4*)g_key;
        float sa = 0.0f, sb = 0.0f, sc = 0.0f, sd = 0.0f;
        for (int i = tid; i < NKEYS / 4; i += THREADS) {
            uint4 v = __ldcg(&kp[i]);
            sa += __uint_as_float(v.x);
            sb += __uint_as_float(v.y);
            sc += __uint_as_float(v.z);
            sd += __uint_as_float(v.w);
        }
        float s = (sa + sb) + (sc + sd);
        #pragma unroll
        for (int off = 16; off > 0; off >>= 1)
            s += __shfl_xor_sync(0xffffffffu, s, off);
        if ((tid & 31) == 0) wsum[tid >> 5] = s;
        __syncthreads();
        if (tid == 0) {
            float t = 0.0f;
            #pragma unroll
            for (int i = 0; i < THREADS / 32; i++) t += wsum[i];
            // min dist per query = -2 * t_full; two means each over B*NPTS
            out[0] = t * (-2.0f / (float)(NBATCH * NPTS));
        }
    }
}

extern "C" void kernel_launch(void* const* d_in, const int* in_sizes, int n_in,
                              void* d_out, int out_size) {
    const float* pred = (const float*)d_in[0];
    const float* targ = (const float*)d_in[1];
    float* out = (float*)d_out;

    chamfer_init_kernel<<<NKEYS / 256, 256>>>();
    chamfer_main_kernel<<<NBLOCKS, THREADS>>>(pred, targ, out);
}